// round 10
// baseline (speedup 1.0000x reference)
#include <cuda_runtime.h>
#include <cuda_bf16.h>
#include <cstdint>
#include <float.h>

typedef __nv_bfloat16 bf16;

// Problem constants
#define BB    2
#define NN    1024
#define MDOC  4
#define JJ    4096
#define DIMM  1024
#define HH    8
#define HD    128

// ---------------------------------------------------------------------------
// Device-global scratch (allocation-free rule)
// ---------------------------------------------------------------------------
__device__ bf16 g_xh[2048*1024],  g_xl[2048*1024];
__device__ bf16 g_ch[8192*1024],  g_cl[8192*1024];
__device__ bf16 g_Wqh[1024*1024], g_Wql[1024*1024];
__device__ bf16 g_Wkvh[2048*1024],g_Wkvl[2048*1024];
__device__ bf16 g_Woh[1024*1024], g_Wol[1024*1024];
__device__ bf16 g_qh[2048*1024],  g_ql[2048*1024];   // [b,h,n,d]
__device__ bf16 g_kh[8388608],    g_kl[8388608];     // [b,h,j,d]
__device__ bf16 g_vh[8388608],    g_vl[8388608];     // [b,h,j,d]
__device__ bf16 g_aoh[2048*1024], g_aol[2048*1024];  // [b*n, dim]

// ---------------------------------------------------------------------------
// PTX helpers
// ---------------------------------------------------------------------------
__device__ __forceinline__ void mma16816(float* c, const uint32_t* a, const uint32_t* b) {
    asm volatile(
        "mma.sync.aligned.m16n8k16.row.col.f32.bf16.bf16.f32 "
        "{%0,%1,%2,%3}, {%4,%5,%6,%7}, {%8,%9}, {%0,%1,%2,%3};\n"
        : "+f"(c[0]), "+f"(c[1]), "+f"(c[2]), "+f"(c[3])
        : "r"(a[0]), "r"(a[1]), "r"(a[2]), "r"(a[3]), "r"(b[0]), "r"(b[1]));
}
__device__ __forceinline__ uint32_t smu(const void* p) {
    return (uint32_t)__cvta_generic_to_shared(p);
}
__device__ __forceinline__ void cp16(uint32_t d, const void* s) {
    asm volatile("cp.async.cg.shared.global [%0], [%1], 16;\n" :: "r"(d), "l"(s));
}
__device__ __forceinline__ void cp_commit() {
    asm volatile("cp.async.commit_group;\n");
}
template<int N> __device__ __forceinline__ void cp_wait() {
    asm volatile("cp.async.wait_group %0;\n" :: "n"(N));
}
__device__ __forceinline__ void ldsm4(uint32_t* r, uint32_t a) {
    asm volatile("ldmatrix.sync.aligned.m8n8.x4.shared.b16 {%0,%1,%2,%3}, [%4];\n"
        : "=r"(r[0]), "=r"(r[1]), "=r"(r[2]), "=r"(r[3]) : "r"(a));
}
__device__ __forceinline__ void ldsm4t(uint32_t* r, uint32_t a) {
    asm volatile("ldmatrix.sync.aligned.m8n8.x4.trans.shared.b16 {%0,%1,%2,%3}, [%4];\n"
        : "=r"(r[0]), "=r"(r[1]), "=r"(r[2]), "=r"(r[3]) : "r"(a));
}
__device__ __forceinline__ void split2(float v, bf16& h, bf16& l) {
    h = __float2bfloat16(v);
    l = __float2bfloat16(v - __bfloat162float(h));
}
__device__ __forceinline__ void pack2(float a, float b, uint32_t& hi, uint32_t& lo) {
    bf16 ha,la,hb,lb; split2(a,ha,la); split2(b,hb,lb);
    __nv_bfloat162 th, tl;
    th.x=ha; th.y=hb; tl.x=la; tl.y=lb;
    hi = *(uint32_t*)&th; lo = *(uint32_t*)&tl;
}

// ---------------------------------------------------------------------------
// fp32 -> (hi, lo) bf16 split conversion
// ---------------------------------------------------------------------------
__global__ void split_kernel(const float* __restrict__ in, bf16* __restrict__ hi,
                             bf16* __restrict__ lo, int n4)
{
    int i = blockIdx.x * blockDim.x + threadIdx.x;
    if (i >= n4) return;
    float4 v = ((const float4*)in)[i];
    bf16 h0,h1,h2,h3,l0,l1,l2,l3;
    split2(v.x,h0,l0); split2(v.y,h1,l1); split2(v.z,h2,l2); split2(v.w,h3,l3);
    __nv_bfloat162 a,b;
    a.x=h0; a.y=h1; b.x=h2; b.y=h3;
    *(__nv_bfloat162*)&hi[4*i]   = a;
    *(__nv_bfloat162*)&hi[4*i+2] = b;
    a.x=l0; a.y=l1; b.x=l2; b.y=l3;
    *(__nv_bfloat162*)&lo[4*i]   = a;
    *(__nv_bfloat162*)&lo[4*i+2] = b;
}

// ---------------------------------------------------------------------------
// Split-bf16 GEMM v3: C[M,N] = A[M,K] @ B[N,K]^T
// 128x128 tile, BK=32, 3-stage cp.async pipeline, 256 threads,
// warp tile 32x64 (4 row-warps x 2 col-warps).
// MODE 0: fp32 out + bias. MODE 1: q split head-major. MODE 2: kv split.
// ---------------------------------------------------------------------------
#define TM 128
#define TN 128
#define TBK 32
#define PSTR 40                               // bf16 row stride (80 B)
#define GSTAGE (4*TM*PSTR)                    // bf16 elems/stage: Ah,Al,Bh,Bl (20480)
#define NSTAGE 3
#define GEMM_SMEM (NSTAGE*GSTAGE*2)           // 122880 bytes

template<int MODE>
__global__ __launch_bounds__(256, 1)
void gemm_split(const bf16* __restrict__ Ah, const bf16* __restrict__ Al,
                const bf16* __restrict__ Bh, const bf16* __restrict__ Bl,
                int K, float* __restrict__ C, int ldc,
                const float* __restrict__ bias,
                bf16* __restrict__ O1h, bf16* __restrict__ O1l,
                bf16* __restrict__ O2h, bf16* __restrict__ O2l)
{
    extern __shared__ bf16 smg[];

    const int tid  = threadIdx.x;
    const int lane = tid & 31, w = tid >> 5;
    const int g = lane >> 2, p = lane & 3;
    const int mwr = (w & 3) * 32;             // warp row base
    const int nwr = (w >> 2) * 64;            // warp col base (2 warps x 64)
    const int m0 = blockIdx.y * TM, n0 = blockIdx.x * TN;

    float acc[2][8][4];
#pragma unroll
    for (int a = 0; a < 2; a++)
#pragma unroll
        for (int b = 0; b < 8; b++)
#pragma unroll
            for (int c = 0; c < 4; c++) acc[a][b][c] = 0.f;

    const int NT = K / TBK;

    auto load_stage = [&](int t, int s) {
        bf16* sAh = smg + s * GSTAGE;
        bf16* sAl = sAh + TM * PSTR;
        bf16* sBh = sAl + TM * PSTR;
        bf16* sBl = sBh + TN * PSTR;
        const int k0 = t * TBK;
#pragma unroll
        for (int i = 0; i < 2; i++) {
            int idx = tid + i * 256;          // 0..511
            int r = idx >> 2, c8 = (idx & 3) * 8;
            size_t ga = (size_t)(m0 + r) * K + k0 + c8;
            size_t gb = (size_t)(n0 + r) * K + k0 + c8;
            int d = r * PSTR + c8;
            cp16(smu(&sAh[d]), &Ah[ga]);
            cp16(smu(&sAl[d]), &Al[ga]);
            cp16(smu(&sBh[d]), &Bh[gb]);
            cp16(smu(&sBl[d]), &Bl[gb]);
        }
        cp_commit();
    };

    load_stage(0, 0);
    load_stage(1, 1);
    load_stage(2, 2);

    for (int t = 0; t < NT; t++) {
        cp_wait<2>();
        __syncthreads();

        const int s = t % NSTAGE;
        bf16* sAh = smg + s * GSTAGE;
        bf16* sAl = sAh + TM * PSTR;
        bf16* sBh = sAl + TM * PSTR;
        bf16* sBl = sBh + TN * PSTR;

#pragma unroll
        for (int ks = 0; ks < 2; ks++) {
            const int kb = ks * 16;
            uint32_t ah[2][4], al[2][4];
#pragma unroll
            for (int mt = 0; mt < 2; mt++) {
                int aoff = (mwr + mt*16 + (lane & 15)) * PSTR + kb + (lane >> 4) * 8;
                ldsm4(ah[mt], smu(&sAh[aoff]));
                ldsm4(al[mt], smu(&sAl[aoff]));
            }
#pragma unroll
            for (int np = 0; np < 4; np++) {
                int boff = (nwr + np*16 + ((lane >> 4) << 3) + (lane & 7)) * PSTR
                         + kb + ((lane >> 3) & 1) * 8;
                uint32_t bh[4], bl[4];
                ldsm4(bh, smu(&sBh[boff]));
                ldsm4(bl, smu(&sBl[boff]));
#pragma unroll
                for (int h2 = 0; h2 < 2; h2++) {
#pragma unroll
                    for (int mt = 0; mt < 2; mt++) {
                        float* ac = acc[mt][np*2 + h2];
                        mma16816(ac, ah[mt], &bh[h2*2]);
                        mma16816(ac, ah[mt], &bl[h2*2]);
                        mma16816(ac, al[mt], &bh[h2*2]);
                    }
                }
            }
        }
        __syncthreads();
        if (t + NSTAGE < NT) load_stage(t + NSTAGE, s);
    }

    // ---- epilogue ----
#pragma unroll
    for (int mt = 0; mt < 2; mt++)
#pragma unroll
    for (int nf = 0; nf < 8; nf++)
#pragma unroll
    for (int half = 0; half < 2; half++) {
        int rm = m0 + mwr + mt*16 + g + half*8;
        int cg = n0 + nwr + nf*8 + 2*p;
        float v0 = acc[mt][nf][half*2];
        float v1 = acc[mt][nf][half*2 + 1];
        if (MODE == 0) {
            v0 += bias[cg]; v1 += bias[cg+1];
            float2 f2; f2.x = v0; f2.y = v1;
            *(float2*)&C[(size_t)rm*ldc + cg] = f2;
        } else if (MODE == 1) {
            int b = rm >> 10, n = rm & 1023;
            int hh = cg >> 7, d = cg & 127;
            size_t idx = (((size_t)(b*HH + hh))*NN + n)*HD + d;
            uint32_t hi, lo; pack2(v0, v1, hi, lo);
            *(uint32_t*)&O1h[idx] = hi;
            *(uint32_t*)&O1l[idx] = lo;
        } else {
            int b = rm >> 12, j = rm & 4095;
            int cc = cg;
            bf16 *dh, *dl;
            if (cc < 1024) { dh = O1h; dl = O1l; }
            else           { cc -= 1024; dh = O2h; dl = O2l; }
            int hh = cc >> 7, d = cc & 127;
            size_t idx = (((size_t)(b*HH + hh))*JJ + j)*HD + d;
            uint32_t hi, lo; pack2(v0, v1, hi, lo);
            *(uint32_t*)&dh[idx] = hi;
            *(uint32_t*)&dl[idx] = lo;
        }
    }
}

// ---------------------------------------------------------------------------
// Flash attention (FA2-style): BQ=64, BJ=32, 128 threads, 2 CTAs/SM.
// (unchanged from round 8, the 778us version)
// ---------------------------------------------------------------------------
#define AQ 64
#define AJ 32
#define QST 136
#define OFFB_QL   (AQ*QST*2)
#define OFFB_STG  (2*AQ*QST*2)
#define STGB      (4*AJ*QST*2)
#define OFFB_MISC (OFFB_STG + 2*STGB)
#define ATTN_SMEM (OFFB_MISC + 96*4)

__global__ __launch_bounds__(128, 2)
void attn_mma(const bf16* __restrict__ qh, const bf16* __restrict__ ql,
              const bf16* __restrict__ kh, const bf16* __restrict__ kl,
              const bf16* __restrict__ vh, const bf16* __restrict__ vl,
              const float* __restrict__ ds, const int* __restrict__ mask,
              const int* __restrict__ cmask, const float* __restrict__ betap,
              bf16* __restrict__ aoh, bf16* __restrict__ aol)
{
    extern __shared__ char smc[];
    bf16* sQh = (bf16*)smc;
    bf16* sQl = (bf16*)(smc + OFFB_QL);
    float* s_rok = (float*)(smc + OFFB_MISC);
    float* s_cok = s_rok + 64;

    const int tid  = threadIdx.x;
    const int lane = tid & 31, w = tid >> 5;
    const int g = lane >> 2, p = lane & 3;
    const int b = blockIdx.z, h = blockIdx.y, q0 = blockIdx.x * AQ;
    const float beta  = *betap;
    const float scale = 0.03125f;
    const int rbase = w * 16;

    const size_t qbase  = (((size_t)(b*HH + h))*NN + q0)*HD;
    const size_t kvbase = ((size_t)(b*HH + h))*JJ*HD;

    float sim_arr[4];
#pragma unroll
    for (int i = 0; i < 4; i++) sim_arr[i] = ds[b*MDOC + i] * beta;

#pragma unroll
    for (int i = 0; i < 8; i++) {
        int li = tid + i * 128;
        int r = li >> 4, c8 = (li & 15) * 8;
        *(uint4*)&sQh[r*QST + c8] = *(const uint4*)&qh[qbase + (size_t)r*HD + c8];
        *(uint4*)&sQl[r*QST + c8] = *(const uint4*)&ql[qbase + (size_t)r*HD + c8];
    }
    if (tid < 64) s_rok[tid] = (mask[b*NN + q0 + tid] != 0) ? 1.f : 0.f;

    auto load_stage = [&](int jt, int s) {
        bf16* stg = (bf16*)(smc + OFFB_STG + s * STGB);
        bf16* dKh = stg;
        bf16* dKl = stg + AJ*QST;
        bf16* dVh = stg + 2*AJ*QST;
        bf16* dVl = stg + 3*AJ*QST;
        const size_t src0 = kvbase + (size_t)(jt * AJ) * HD;
#pragma unroll
        for (int i = 0; i < 4; i++) {
            int c = tid + i * 128;
            int r = c >> 4, c8 = (c & 15) * 8;
            size_t src = src0 + (size_t)r * HD + c8;
            int dst = r*QST + c8;
            cp16(smu(&dKh[dst]), &kh[src]);
            cp16(smu(&dKl[dst]), &kl[src]);
            cp16(smu(&dVh[dst]), &vh[src]);
            cp16(smu(&dVl[dst]), &vl[src]);
        }
        cp_commit();
    };

    load_stage(0, 0);
    __syncthreads();

    uint32_t qfh[8][4], qfl[8][4];
#pragma unroll
    for (int ks = 0; ks < 8; ks++) {
        int aoff = (rbase + (lane & 15)) * QST + ks*16 + (lane >> 4) * 8;
        ldsm4(qfh[ks], smu(&sQh[aoff]));
        ldsm4(qfl[ks], smu(&sQl[aoff]));
    }

    const float rok0 = s_rok[rbase + g];
    const float rok1 = s_rok[rbase + g + 8];
    float m0 = -FLT_MAX, m1 = -FLT_MAX, l0 = 0.f, l1 = 0.f;

    float O[16][4];
#pragma unroll
    for (int a = 0; a < 16; a++)
#pragma unroll
        for (int c = 0; c < 4; c++) O[a][c] = 0.f;

    const int NTILE = JJ / AJ;
    for (int jt = 0; jt < NTILE; jt++) {
        if (jt + 1 < NTILE) { load_stage(jt + 1, (jt + 1) & 1); cp_wait<1>(); }
        else                { cp_wait<0>(); }
        if (tid < AJ)
            s_cok[tid] = (cmask[b*JJ + jt*AJ + tid] != 0) ? 1.f : 0.f;
        __syncthreads();

        bf16* stg = (bf16*)(smc + OFFB_STG + (jt & 1) * STGB);
        bf16* sKh = stg;
        bf16* sKl = stg + AJ*QST;
        bf16* sVh = stg + 2*AJ*QST;
        bf16* sVl = stg + 3*AJ*QST;

        float SA[4][4];
#pragma unroll
        for (int nf = 0; nf < 4; nf++)
#pragma unroll
            for (int c = 0; c < 4; c++) SA[nf][c] = 0.f;
#pragma unroll
        for (int ks = 0; ks < 8; ks++) {
            const int kb = ks * 16;
            uint32_t bh0[4], bl0[4], bh1[4], bl1[4];
            int b0 = (((lane >> 4) << 3) + (lane & 7)) * QST + kb + ((lane >> 3) & 1) * 8;
            int b1 = b0 + 16 * QST;
            ldsm4(bh0, smu(&sKh[b0]));
            ldsm4(bl0, smu(&sKl[b0]));
            ldsm4(bh1, smu(&sKh[b1]));
            ldsm4(bl1, smu(&sKl[b1]));
            mma16816(SA[0], qfh[ks], &bh0[0]);
            mma16816(SA[0], qfh[ks], &bl0[0]);
            mma16816(SA[0], qfl[ks], &bh0[0]);
            mma16816(SA[1], qfh[ks], &bh0[2]);
            mma16816(SA[1], qfh[ks], &bl0[2]);
            mma16816(SA[1], qfl[ks], &bh0[2]);
            mma16816(SA[2], qfh[ks], &bh1[0]);
            mma16816(SA[2], qfh[ks], &bl1[0]);
            mma16816(SA[2], qfl[ks], &bh1[0]);
            mma16816(SA[3], qfh[ks], &bh1[2]);
            mma16816(SA[3], qfh[ks], &bl1[2]);
            mma16816(SA[3], qfl[ks], &bh1[2]);
        }

        const float simt = sim_arr[jt >> 5];
        float sv0[8], sv1[8];
#pragma unroll
        for (int nf = 0; nf < 4; nf++) {
            float ck0 = s_cok[nf*8 + 2*p];
            float ck1 = s_cok[nf*8 + 2*p + 1];
            sv0[2*nf]   = (rok0 > 0.5f && ck0 > 0.5f) ? SA[nf][0]*scale + simt : -FLT_MAX;
            sv0[2*nf+1] = (rok0 > 0.5f && ck1 > 0.5f) ? SA[nf][1]*scale + simt : -FLT_MAX;
            sv1[2*nf]   = (rok1 > 0.5f && ck0 > 0.5f) ? SA[nf][2]*scale + simt : -FLT_MAX;
            sv1[2*nf+1] = (rok1 > 0.5f && ck1 > 0.5f) ? SA[nf][3]*scale + simt : -FLT_MAX;
        }
        float mx0 = -FLT_MAX, mx1 = -FLT_MAX;
#pragma unroll
        for (int c = 0; c < 8; c++) { mx0 = fmaxf(mx0, sv0[c]); mx1 = fmaxf(mx1, sv1[c]); }
        mx0 = fmaxf(mx0, __shfl_xor_sync(0xffffffffu, mx0, 1));
        mx0 = fmaxf(mx0, __shfl_xor_sync(0xffffffffu, mx0, 2));
        mx1 = fmaxf(mx1, __shfl_xor_sync(0xffffffffu, mx1, 1));
        mx1 = fmaxf(mx1, __shfl_xor_sync(0xffffffffu, mx1, 2));
        float mn0 = fmaxf(m0, mx0), mn1 = fmaxf(m1, mx1);
        float f0 = __expf(m0 - mn0), f1 = __expf(m1 - mn1);
        m0 = mn0; m1 = mn1;
        float pv0[8], pv1[8], sm0 = 0.f, sm1 = 0.f;
#pragma unroll
        for (int c = 0; c < 8; c++) {
            pv0[c] = __expf(sv0[c] - mn0); sm0 += pv0[c];
            pv1[c] = __expf(sv1[c] - mn1); sm1 += pv1[c];
        }
        sm0 += __shfl_xor_sync(0xffffffffu, sm0, 1);
        sm0 += __shfl_xor_sync(0xffffffffu, sm0, 2);
        sm1 += __shfl_xor_sync(0xffffffffu, sm1, 1);
        sm1 += __shfl_xor_sync(0xffffffffu, sm1, 2);
        l0 = l0*f0 + sm0;
        l1 = l1*f1 + sm1;

        uint32_t pah[2][4], pal[2][4];
#pragma unroll
        for (int kf = 0; kf < 2; kf++) {
            int bs = kf * 4;
            pack2(pv0[bs+0], pv0[bs+1], pah[kf][0], pal[kf][0]);
            pack2(pv1[bs+0], pv1[bs+1], pah[kf][1], pal[kf][1]);
            pack2(pv0[bs+2], pv0[bs+3], pah[kf][2], pal[kf][2]);
            pack2(pv1[bs+2], pv1[bs+3], pah[kf][3], pal[kf][3]);
        }

#pragma unroll
        for (int nf = 0; nf < 16; nf++) {
            O[nf][0] *= f0; O[nf][1] *= f0;
            O[nf][2] *= f1; O[nf][3] *= f1;
        }
#pragma unroll
        for (int kf = 0; kf < 2; kf++) {
            const int kb = kf * 16;
#pragma unroll
            for (int dp = 0; dp < 8; dp++) {
                int boff = (kb + ((lane >> 3) & 1) * 8 + (lane & 7)) * QST
                         + dp*16 + (lane >> 4) * 8;
                uint32_t vbh[4], vbl[4];
                ldsm4t(vbh, smu(&sVh[boff]));
                ldsm4t(vbl, smu(&sVl[boff]));
#pragma unroll
                for (int h2 = 0; h2 < 2; h2++) {
                    float* ac = O[dp*2 + h2];
                    mma16816(ac, pah[kf], &vbh[h2*2]);
                    mma16816(ac, pah[kf], &vbl[h2*2]);
                    mma16816(ac, pal[kf], &vbh[h2*2]);
                }
            }
        }
        __syncthreads();
    }

    float i0 = 1.f / l0;
    float i1 = 1.f / l1;
#pragma unroll
    for (int nf = 0; nf < 16; nf++) {
        int col = h*HD + nf*8 + 2*p;
        int row0 = q0 + rbase + g;
        size_t idx0 = (size_t)(b*NN + row0)*DIMM + col;
        uint32_t hi, lo;
        pack2(O[nf][0]*i0, O[nf][1]*i0, hi, lo);
        *(uint32_t*)&aoh[idx0] = hi;
        *(uint32_t*)&aol[idx0] = lo;
        size_t idx1 = (size_t)(b*NN + row0 + 8)*DIMM + col;
        pack2(O[nf][2]*i1, O[nf][3]*i1, hi, lo);
        *(uint32_t*)&aoh[idx1] = hi;
        *(uint32_t*)&aol[idx1] = lo;
    }
}

// ---------------------------------------------------------------------------
extern "C" void kernel_launch(void* const* d_in, const int* in_sizes, int n_in,
                              void* d_out, int out_size)
{
    const float* x     = (const float*)d_in[0];
    const float* ctx   = (const float*)d_in[1];
    const float* dsim  = (const float*)d_in[2];
    const int*   mask  = (const int*)d_in[3];
    const int*   cmask = (const int*)d_in[4];
    const float* Wq    = (const float*)d_in[5];
    const float* Wkv   = (const float*)d_in[6];
    const float* beta  = (const float*)d_in[7];
    const float* Wout  = (const float*)d_in[8];
    const float* bout  = (const float*)d_in[9];
    float* out = (float*)d_out;

    bf16 *xh,*xl,*ch,*cl,*Wqh,*Wql,*Wkvh,*Wkvl,*Woh,*Wol;
    bf16 *qh,*ql,*kh,*kl,*vh,*vl,*aoh,*aol;
    cudaGetSymbolAddress((void**)&xh, g_xh);   cudaGetSymbolAddress((void**)&xl, g_xl);
    cudaGetSymbolAddress((void**)&ch, g_ch);   cudaGetSymbolAddress((void**)&cl, g_cl);
    cudaGetSymbolAddress((void**)&Wqh, g_Wqh); cudaGetSymbolAddress((void**)&Wql, g_Wql);
    cudaGetSymbolAddress((void**)&Wkvh, g_Wkvh); cudaGetSymbolAddress((void**)&Wkvl, g_Wkvl);
    cudaGetSymbolAddress((void**)&Woh, g_Woh); cudaGetSymbolAddress((void**)&Wol, g_Wol);
    cudaGetSymbolAddress((void**)&qh, g_qh);   cudaGetSymbolAddress((void**)&ql, g_ql);
    cudaGetSymbolAddress((void**)&kh, g_kh);   cudaGetSymbolAddress((void**)&kl, g_kl);
    cudaGetSymbolAddress((void**)&vh, g_vh);   cudaGetSymbolAddress((void**)&vl, g_vl);
    cudaGetSymbolAddress((void**)&aoh, g_aoh); cudaGetSymbolAddress((void**)&aol, g_aol);

    cudaFuncSetAttribute(gemm_split<0>, cudaFuncAttributeMaxDynamicSharedMemorySize, GEMM_SMEM);
    cudaFuncSetAttribute(gemm_split<1>, cudaFuncAttributeMaxDynamicSharedMemorySize, GEMM_SMEM);
    cudaFuncSetAttribute(gemm_split<2>, cudaFuncAttributeMaxDynamicSharedMemorySize, GEMM_SMEM);
    cudaFuncSetAttribute(attn_mma, cudaFuncAttributeMaxDynamicSharedMemorySize, ATTN_SMEM);

    // splits
    split_kernel<<<(2048*1024/4)/256, 256>>>(x,   xh,  xl,  2048*1024/4);
    split_kernel<<<(8192*1024/4)/256, 256>>>(ctx, ch,  cl,  8192*1024/4);
    split_kernel<<<(1024*1024/4)/256, 256>>>(Wq,  Wqh, Wql, 1024*1024/4);
    split_kernel<<<(2048*1024/4)/256, 256>>>(Wkv, Wkvh,Wkvl,2048*1024/4);
    split_kernel<<<(1024*1024/4)/256, 256>>>(Wout,Woh, Wol, 1024*1024/4);

    // q = x @ Wq^T  -> q split head-major
    gemm_split<1><<<dim3(1024/TN, 2048/TM), 256, GEMM_SMEM>>>(
        xh, xl, Wqh, Wql, 1024, nullptr, 0, nullptr, qh, ql, nullptr, nullptr);

    // kv = ctx @ Wkv^T -> k,v split head-major
    gemm_split<2><<<dim3(2048/TN, 8192/TM), 256, GEMM_SMEM>>>(
        ch, cl, Wkvh, Wkvl, 1024, nullptr, 0, nullptr, kh, kl, vh, vl);

    // attention (128 threads, 2 CTAs/SM, single wave)
    attn_mma<<<dim3(NN/AQ, HH, BB), 128, ATTN_SMEM>>>(
        qh, ql, kh, kl, vh, vl, dsim, mask, cmask, beta, aoh, aol);

    // out = ao @ Wout^T + bout
    gemm_split<0><<<dim3(1024/TN, 2048/TM), 256, GEMM_SMEM>>>(
        aoh, aol, Woh, Wol, 1024, out, 1024, bout, nullptr, nullptr, nullptr, nullptr);
}